// round 12
// baseline (speedup 1.0000x reference)
#include <cuda_runtime.h>
#include <cuda_bf16.h>
#include <math.h>
#include <stdint.h>

#define NB   8
#define CDIM 256
#define CKD  64
#define NN   4096

// ---------------------------------------------------------------------------
// Scratch (allocation-free rule: __device__ globals). All split bf16 hi/lo.
// ---------------------------------------------------------------------------
__device__ __nv_bfloat16 g_xh[NB * CDIM * NN], g_xl[NB * CDIM * NN];
__device__ __nv_bfloat16 g_Qh[NB * CKD  * NN], g_Ql[NB * CKD  * NN];
__device__ __nv_bfloat16 g_Kh[NB * CKD  * NN], g_Kl[NB * CKD  * NN];
__device__ __nv_bfloat16 g_Vh[NB * CDIM * NN], g_Vl[NB * CDIM * NN];
__device__ __nv_bfloat16 g_Oh[NB * CDIM * NN], g_Ol[NB * CDIM * NN];
__device__ __nv_bfloat16 g_Wqh[CKD * CDIM],  g_Wql[CKD * CDIM];
__device__ __nv_bfloat16 g_Wkh[CKD * CDIM],  g_Wkl[CKD * CDIM];
__device__ __nv_bfloat16 g_Wvh[CDIM * CDIM], g_Wvl[CDIM * CDIM];
__device__ __nv_bfloat16 g_Wgh[CDIM * CDIM], g_Wgl[CDIM * CDIM];

// ---------------------------------------------------------------------------
// Helpers (fragment maps validated R4-R6)
// ---------------------------------------------------------------------------
__device__ __forceinline__ float elu_scaled(float x) {
    const float invN = 1.0f / 4096.0f;
    return (x > 0.f ? x : (expf(x) - 1.f)) * invN;
}
__device__ __forceinline__ void split2(float x, __nv_bfloat16& h, __nv_bfloat16& l) {
    h = __float2bfloat16(x);
    l = __float2bfloat16(x - __bfloat162float(h));
}
__device__ __forceinline__ uint32_t cvta_s(const void* p) {
    return (uint32_t)__cvta_generic_to_shared(p);
}
__device__ __forceinline__ void ldsm_x4(uint32_t* r, uint32_t addr) {
    asm volatile("ldmatrix.sync.aligned.m8n8.x4.shared.b16 {%0,%1,%2,%3},[%4];\n"
                 : "=r"(r[0]), "=r"(r[1]), "=r"(r[2]), "=r"(r[3]) : "r"(addr));
}
__device__ __forceinline__ void ldsm_x4_t(uint32_t* r, uint32_t addr) {
    asm volatile("ldmatrix.sync.aligned.m8n8.x4.trans.shared.b16 {%0,%1,%2,%3},[%4];\n"
                 : "=r"(r[0]), "=r"(r[1]), "=r"(r[2]), "=r"(r[3]) : "r"(addr));
}
__device__ __forceinline__ void mma_bf16(float* c, const uint32_t* a, const uint32_t* b) {
    asm volatile(
        "mma.sync.aligned.m16n8k16.row.col.f32.bf16.bf16.f32 "
        "{%0,%1,%2,%3},{%4,%5,%6,%7},{%8,%9},{%0,%1,%2,%3};\n"
        : "+f"(c[0]), "+f"(c[1]), "+f"(c[2]), "+f"(c[3])
        : "r"(a[0]), "r"(a[1]), "r"(a[2]), "r"(a[3]), "r"(b[0]), "r"(b[1]));
}
__device__ __forceinline__ void cp16(uint32_t saddr, const void* g) {
    asm volatile("cp.async.cg.shared.global [%0],[%1],16;\n" :: "r"(saddr), "l"(g));
}
__device__ __forceinline__ void cp_commit() {
    asm volatile("cp.async.commit_group;\n" ::: "memory");
}
template <int N> __device__ __forceinline__ void cp_wait() {
    asm volatile("cp.async.wait_group %0;\n" :: "n"(N) : "memory");
}
__device__ __forceinline__ uint32_t sw128(uint32_t off) {   // byte-offset swizzle
    return off ^ ((off >> 3) & 0x70);
}

// ---------------------------------------------------------------------------
// Split fp32 -> bf16 hi/lo.
// ---------------------------------------------------------------------------
__global__ __launch_bounds__(256) void split_kernel(
    const float4* __restrict__ in, __nv_bfloat162* __restrict__ oh,
    __nv_bfloat162* __restrict__ ol, int n4)
{
    int i = blockIdx.x * blockDim.x + threadIdx.x;
    if (i >= n4) return;
    float4 v = in[i];
    __nv_bfloat16 h0, l0, h1, l1, h2, l2, h3, l3;
    split2(v.x, h0, l0); split2(v.y, h1, l1);
    split2(v.z, h2, l2); split2(v.w, h3, l3);
    __nv_bfloat162 a, b;
    a.x = h0; a.y = h1; b.x = h2; b.y = h3;
    oh[i * 2] = a; oh[i * 2 + 1] = b;
    a.x = l0; a.y = l1; b.x = l2; b.y = l3;
    ol[i * 2] = a; ol[i * 2 + 1] = b;
}

// ---------------------------------------------------------------------------
// Tensor-core projection (R6-validated, unchanged): Y = W X + bias
// ---------------------------------------------------------------------------
#define WLD 72
#define XLD 136

__global__ __launch_bounds__(256) void proj_mma_kernel(
    const __nv_bfloat16* __restrict__ Wh_g, const __nv_bfloat16* __restrict__ Wl_g,
    const float* __restrict__ bias,
    const __nv_bfloat16* __restrict__ Xh, const __nv_bfloat16* __restrict__ Xl,
    __nv_bfloat16* __restrict__ Yh, __nv_bfloat16* __restrict__ Yl,
    float* __restrict__ Yf, int R)
{
    extern __shared__ __nv_bfloat16 sp[];
    __nv_bfloat16* Wh   = sp;
    __nv_bfloat16* Wl   = Wh + 64 * WLD;
    __nv_bfloat16* Xbuf = Wl + 64 * WLD;

    const int b  = blockIdx.z;
    const int o0 = blockIdx.y * 64;
    const int n0 = blockIdx.x * 128;
    const int tid  = threadIdx.x;
    const int warp = tid >> 5;
    const int lane = tid & 31;

    const __nv_bfloat16* Xbh = Xh + (size_t)b * CDIM * NN;
    const __nv_bfloat16* Xbl = Xl + (size_t)b * CDIM * NN;

    const uint32_t wh_b = cvta_s(Wh), wl_b = cvta_s(Wl);
    const uint32_t x_b  = cvta_s(Xbuf);
    const uint32_t xstride = 2u * 64 * XLD * 2;

    auto issueX = [&](int kc, int buf) {
#pragma unroll
        for (int r = 0; r < 4; ++r) {
            int idx = tid + r * 256;
            int row = idx >> 4, c4 = idx & 15;
            uint32_t dh = x_b + buf * xstride + (uint32_t)(row * XLD + c4 * 8) * 2;
            cp16(dh, Xbh + (size_t)(kc * 64 + row) * NN + n0 + c4 * 8);
            cp16(dh + 64 * XLD * 2, Xbl + (size_t)(kc * 64 + row) * NN + n0 + c4 * 8);
        }
    };

    const int l7 = lane & 7, rr = lane >> 3;
    const int a_kofs = ((rr & 2) << 2) + l7;
    const int a_mofs = ((rr & 1) << 3);
    const int b_kofs = ((rr & 1) << 3) + l7;
    const int b_nofs = ((rr & 2) << 2);

    const int wo = warp >> 1;
    const int wn = warp & 1;

    float acc[8][4];
#pragma unroll
    for (int t = 0; t < 8; ++t)
#pragma unroll
        for (int e = 0; e < 4; ++e) acc[t][e] = 0.f;

    issueX(0, 0);
    cp_commit();

    for (int kc = 0; kc < 4; ++kc) {
        const int buf = kc & 1;
#pragma unroll
        for (int r = 0; r < 16; ++r) {
            int idx = tid + r * 256;
            int o = idx >> 6, cc = idx & 63;
            Wh[cc * WLD + o] = Wh_g[(size_t)(o0 + o) * CDIM + kc * 64 + cc];
            Wl[cc * WLD + o] = Wl_g[(size_t)(o0 + o) * CDIM + kc * 64 + cc];
        }
        if (kc < 3) { issueX(kc + 1, buf ^ 1); cp_commit(); cp_wait<1>(); }
        else        { cp_wait<0>(); }
        __syncthreads();

        const uint32_t xh_cur = x_b + buf * xstride;
        const uint32_t xl_cur = xh_cur + 64 * XLD * 2;

#pragma unroll
        for (int k0 = 0; k0 < 64; k0 += 16) {
            uint32_t ah[4], al[4];
            uint32_t aoff = (uint32_t)((k0 + a_kofs) * WLD + wo * 16 + a_mofs) * 2;
            ldsm_x4_t(ah, wh_b + aoff);
            ldsm_x4_t(al, wl_b + aoff);
#pragma unroll
            for (int jj = 0; jj < 4; ++jj) {
                uint32_t bh[4], bl[4];
                uint32_t boff =
                    (uint32_t)((k0 + b_kofs) * XLD + wn * 64 + jj * 16 + b_nofs) * 2;
                ldsm_x4_t(bh, xh_cur + boff);
                ldsm_x4_t(bl, xl_cur + boff);
                mma_bf16(acc[jj * 2 + 0], ah, bh + 0);
                mma_bf16(acc[jj * 2 + 0], ah, bl + 0);
                mma_bf16(acc[jj * 2 + 0], al, bh + 0);
                mma_bf16(acc[jj * 2 + 1], ah, bh + 2);
                mma_bf16(acc[jj * 2 + 1], ah, bl + 2);
                mma_bf16(acc[jj * 2 + 1], al, bh + 2);
            }
        }
        __syncthreads();
    }

    const int orow = wo * 16 + (lane >> 2);
    const float b0 = bias[o0 + orow];
    const float b1 = bias[o0 + orow + 8];
#pragma unroll
    for (int t = 0; t < 8; ++t) {
        int col = n0 + wn * 64 + t * 8 + (lane & 3) * 2;
        float v00 = acc[t][0] + b0, v01 = acc[t][1] + b0;
        float v10 = acc[t][2] + b1, v11 = acc[t][3] + b1;
        size_t i0 = ((size_t)b * R + o0 + orow) * NN + col;
        size_t i1 = ((size_t)b * R + o0 + orow + 8) * NN + col;
        if (Yf) {
            *(float2*)&Yf[i0] = make_float2(v00, v01);
            *(float2*)&Yf[i1] = make_float2(v10, v11);
        } else {
            __nv_bfloat16 h0, l0, h1, l1;
            __nv_bfloat162 th, tl;
            split2(v00, h0, l0); split2(v01, h1, l1);
            th.x = h0; th.y = h1; tl.x = l0; tl.y = l1;
            *(__nv_bfloat162*)&Yh[i0] = th;
            *(__nv_bfloat162*)&Yl[i0] = tl;
            split2(v10, h0, l0); split2(v11, h1, l1);
            th.x = h0; th.y = h1; tl.x = l0; tl.y = l1;
            *(__nv_bfloat162*)&Yh[i1] = th;
            *(__nv_bfloat162*)&Yl[i1] = tl;
        }
    }
}

// ---------------------------------------------------------------------------
// Fused attention, 2 CTAs/SM. Per CTA: (b, 64 j). i tiled by 64 (64 iters).
// R6 phase structure; swizzled 128B-row smem (no padding); term-major MMAs.
// smem element offsets (bf16): K 0/4096, Q 8192/12288, P 16384/20480,
//                              V 24576/40960. total 57344 el = 114688 B.
// ---------------------------------------------------------------------------
#define KOF(a)  ((a) * 4096)
#define QOF(a)  (8192 + (a) * 4096)
#define POF(a)  (16384 + (a) * 4096)
#define VOF(a)  (24576 + (a) * 16384)
#define SM_ATTN (57344 * 2)

__global__ __launch_bounds__(256, 2) void attn_bf16_kernel()
{
    extern __shared__ __nv_bfloat16 smb[];
    const uint32_t sb = cvta_s(smb);

    const int b    = blockIdx.y;
    const int j0g  = blockIdx.x * 64;
    const int tid  = threadIdx.x;
    const int warp = tid >> 5;
    const int lane = tid & 31;

    const __nv_bfloat16* Qbh = g_Qh + (size_t)b * CKD * NN;
    const __nv_bfloat16* Qbl = g_Ql + (size_t)b * CKD * NN;
    const __nv_bfloat16* Kbh = g_Kh + (size_t)b * CKD * NN;
    const __nv_bfloat16* Kbl = g_Kl + (size_t)b * CKD * NN;
    const __nv_bfloat16* Vbh = g_Vh + (size_t)b * CDIM * NN;
    const __nv_bfloat16* Vbl = g_Vl + (size_t)b * CDIM * NN;

    const uint32_t kB = sb + KOF(0) * 2;   // arrays adjacent: +8192B for lo
    const uint32_t qB = sb + QOF(0) * 2;
    const uint32_t pB = sb + POF(0) * 2;
    const uint32_t vB = sb + VOF(0) * 2;

    // --- cp.async issuers (swizzled 16B chunks) ---
    auto ldK = [&]() {
#pragma unroll
        for (int r = 0; r < 4; ++r) {
            int idx = tid + r * 256;
            int arr = idx >> 9, q = idx & 511;
            int row = q >> 3, c = q & 7;
            uint32_t d = kB + arr * 8192u + sw128((uint32_t)row * 128 + c * 16);
            const __nv_bfloat16* s =
                (arr ? Kbl : Kbh) + (size_t)row * NN + j0g + c * 8;
            cp16(d, s);
        }
    };
    auto ldQ = [&](int it) {
        int i0 = it * 64;
#pragma unroll
        for (int r = 0; r < 4; ++r) {
            int idx = tid + r * 256;
            int arr = idx >> 9, q = idx & 511;
            int row = q >> 3, c = q & 7;
            uint32_t d = qB + arr * 8192u + sw128((uint32_t)row * 128 + c * 16);
            const __nv_bfloat16* s =
                (arr ? Qbl : Qbh) + (size_t)row * NN + i0 + c * 8;
            cp16(d, s);
        }
    };
    auto ldV = [&](int it) {
        int i0 = it * 64;
#pragma unroll
        for (int r = 0; r < 16; ++r) {
            int idx = tid + r * 256;
            int arr = idx >> 11, q = idx & 2047;
            int row = q >> 3, c = q & 7;
            uint32_t d = vB + arr * 32768u + sw128((uint32_t)row * 128 + c * 16);
            const __nv_bfloat16* s =
                (arr ? Vbl : Vbh) + (size_t)row * NN + i0 + c * 8;
            cp16(d, s);
        }
    };

    // ldmatrix lane components (validated R4)
    const int l7 = lane & 7, rr = lane >> 3;
    const int a_dofs = ((rr & 2) << 2) + l7;   // A-trans: +k
    const int a_iofs = ((rr & 1) << 3);        // A-trans: +m
    const int b_kofs = ((rr & 1) << 3) + l7;   // B-trans: +k
    const int b_jofs = ((rr & 2) << 2);        // B-trans: +n
    const int v_row  = (lane & 15);            // A non-trans: +m
    const int v_col  = ((lane >> 4) << 3);     // A non-trans: +k

    // warp mappings (8 warps)
    const int s_i0 = (warp >> 1) * 16;         // S: 4 i-blocks of 16
    const int s_j0 = (warp & 1) * 32;          // S: 2 j-groups of 32
    const int o_c0 = warp * 32;                // O: 8 c-groups of 32, all 64 j

    float oacc[16][4];                          // [ch*8 + jj*2 + h]
#pragma unroll
    for (int t = 0; t < 16; ++t)
#pragma unroll
        for (int e = 0; e < 4; ++e) oacc[t][e] = 0.f;

    // prologue: K + Q(0)
    ldK();
    ldQ(0);
    cp_commit();
    cp_wait<0>();
    __syncthreads();

    for (int it = 0; it < 64; ++it) {
        // V(it) overlaps the S-phase
        ldV(it);
        cp_commit();

        // ---- S(it) = Q^T K  (warp: 16i x 32j), term-major ----
        float sacc[4][4];
#pragma unroll
        for (int t = 0; t < 4; ++t)
#pragma unroll
            for (int e = 0; e < 4; ++e) sacc[t][e] = 0.f;

#pragma unroll
        for (int k0 = 0; k0 < 64; k0 += 16) {
            uint32_t ah[4], al[4], bh[2][4], bl[2][4];
            uint32_t aoff = sw128((uint32_t)(k0 + a_dofs) * 128 +
                                  (s_i0 + a_iofs) * 2);
            ldsm_x4_t(ah, qB + aoff);
            ldsm_x4_t(al, qB + 8192u + aoff);
#pragma unroll
            for (int jj = 0; jj < 2; ++jj) {
                uint32_t boff = sw128((uint32_t)(k0 + b_kofs) * 128 +
                                      (s_j0 + jj * 16 + b_jofs) * 2);
                ldsm_x4_t(bh[jj], kB + boff);
                ldsm_x4_t(bl[jj], kB + 8192u + boff);
            }
            // hh
            mma_bf16(sacc[0], ah, bh[0] + 0);
            mma_bf16(sacc[1], ah, bh[0] + 2);
            mma_bf16(sacc[2], ah, bh[1] + 0);
            mma_bf16(sacc[3], ah, bh[1] + 2);
            // hl
            mma_bf16(sacc[0], ah, bl[0] + 0);
            mma_bf16(sacc[1], ah, bl[0] + 2);
            mma_bf16(sacc[2], ah, bl[1] + 0);
            mma_bf16(sacc[3], ah, bl[1] + 2);
            // lh
            mma_bf16(sacc[0], al, bh[0] + 0);
            mma_bf16(sacc[1], al, bh[0] + 2);
            mma_bf16(sacc[2], al, bh[1] + 0);
            mma_bf16(sacc[3], al, bh[1] + 2);
        }

        // ---- P(it) = elu(S)/N, split hi/lo -> swizzled P ----
        {
            int prow = s_i0 + (lane >> 2);
#pragma unroll
            for (int t = 0; t < 4; ++t) {
                int jc = s_j0 + (t >> 1) * 16 + (t & 1) * 8 + (lane & 3) * 2;
                float p0 = elu_scaled(sacc[t][0]);
                float p1 = elu_scaled(sacc[t][1]);
                float p2 = elu_scaled(sacc[t][2]);
                float p3 = elu_scaled(sacc[t][3]);
                __nv_bfloat16 h0, l0, h1, l1;
                __nv_bfloat162 th, tl;
                uint32_t o0 = sw128((uint32_t)prow * 128 + jc * 2);
                uint32_t o1 = sw128((uint32_t)(prow + 8) * 128 + jc * 2);
                split2(p0, h0, l0); split2(p1, h1, l1);
                th.x = h0; th.y = h1; tl.x = l0; tl.y = l1;
                *(__nv_bfloat162*)((char*)smb + POF(0) * 2 + o0) = th;
                *(__nv_bfloat162*)((char*)smb + POF(1) * 2 + o0) = tl;
                split2(p2, h0, l0); split2(p3, h1, l1);
                th.x = h0; th.y = h1; tl.x = l0; tl.y = l1;
                *(__nv_bfloat162*)((char*)smb + POF(0) * 2 + o1) = th;
                *(__nv_bfloat162*)((char*)smb + POF(1) * 2 + o1) = tl;
            }
        }
        cp_wait<0>();        // V(it) arrived
        __syncthreads();     // P visible, Q free

        // Q(it+1) overlaps the O-phase
        if (it < 63) { ldQ(it + 1); cp_commit(); }

        // ---- O += V(it) P(it)  (warp: 32c x 64j), term-major per jj ----
#pragma unroll
        for (int k0 = 0; k0 < 64; k0 += 16) {
            uint32_t vh[2][4], vl[2][4];
#pragma unroll
            for (int ch = 0; ch < 2; ++ch) {
                uint32_t voff = sw128((uint32_t)(o_c0 + ch * 16 + v_row) * 128 +
                                      (k0 + v_col) * 2);
                ldsm_x4(vh[ch], vB + voff);
                ldsm_x4(vl[ch], vB + 32768u + voff);
            }
#pragma unroll
            for (int jj = 0; jj < 4; ++jj) {
                uint32_t ph[4], pl[4];
                uint32_t poff = sw128((uint32_t)(k0 + b_kofs) * 128 +
                                      (jj * 16 + b_jofs) * 2);
                ldsm_x4_t(ph, pB + poff);
                ldsm_x4_t(pl, pB + 8192u + poff);
                // hh
                mma_bf16(oacc[0 * 8 + jj * 2 + 0], vh[0], ph + 0);
                mma_bf16(oacc[0 * 8 + jj * 2 + 1], vh[0], ph + 2);
                mma_bf16(oacc[1 * 8 + jj * 2 + 0], vh[1], ph + 0);
                mma_bf16(oacc[1 * 8 + jj * 2 + 1], vh[1], ph + 2);
                // hl
                mma_bf16(oacc[0 * 8 + jj * 2 + 0], vh[0], pl + 0);
                mma_bf16(oacc[0 * 8 + jj * 2 + 1], vh[0], pl + 2);
                mma_bf16(oacc[1 * 8 + jj * 2 + 0], vh[1], pl + 0);
                mma_bf16(oacc[1 * 8 + jj * 2 + 1], vh[1], pl + 2);
                // lh
                mma_bf16(oacc[0 * 8 + jj * 2 + 0], vl[0], ph + 0);
                mma_bf16(oacc[0 * 8 + jj * 2 + 1], vl[0], ph + 2);
                mma_bf16(oacc[1 * 8 + jj * 2 + 0], vl[1], ph + 0);
                mma_bf16(oacc[1 * 8 + jj * 2 + 1], vl[1], ph + 2);
            }
        }
        cp_wait<0>();        // Q(it+1) arrived
        __syncthreads();     // V/P free
    }

    // ---- store O accumulators, split bf16, to scratch ----
#pragma unroll
    for (int ch = 0; ch < 2; ++ch) {
        int orow = o_c0 + ch * 16 + (lane >> 2);
#pragma unroll
        for (int jj = 0; jj < 4; ++jj) {
#pragma unroll
            for (int h = 0; h < 2; ++h) {
                float* a = oacc[ch * 8 + jj * 2 + h];
                int col = j0g + jj * 16 + h * 8 + (lane & 3) * 2;
                size_t i0 = ((size_t)b * CDIM + orow) * NN + col;
                size_t i1 = ((size_t)b * CDIM + orow + 8) * NN + col;
                __nv_bfloat16 h0, l0, h1, l1;
                __nv_bfloat162 th, tl;
                split2(a[0], h0, l0); split2(a[1], h1, l1);
                th.x = h0; th.y = h1; tl.x = l0; tl.y = l1;
                *(__nv_bfloat162*)&g_Oh[i0] = th;
                *(__nv_bfloat162*)&g_Ol[i0] = tl;
                split2(a[2], h0, l0); split2(a[3], h1, l1);
                th.x = h0; th.y = h1; tl.x = l0; tl.y = l1;
                *(__nv_bfloat162*)&g_Oh[i1] = th;
                *(__nv_bfloat162*)&g_Ol[i1] = tl;
            }
        }
    }
}

// ---------------------------------------------------------------------------
extern "C" void kernel_launch(void* const* d_in, const int* in_sizes, int n_in,
                              void* d_out, int out_size)
{
    const float* x  = (const float*)d_in[0];
    const float* wq = (const float*)d_in[1];
    const float* bq = (const float*)d_in[2];
    const float* wk = (const float*)d_in[3];
    const float* bk = (const float*)d_in[4];
    const float* wv = (const float*)d_in[5];
    const float* bv = (const float*)d_in[6];
    const float* wg = (const float*)d_in[7];
    const float* bg = (const float*)d_in[8];
    float* out = (float*)d_out;

    __nv_bfloat16 *xh, *xl, *Qh, *Ql, *Kh, *Kl, *Vh, *Vl, *Oh, *Ol;
    __nv_bfloat16 *Wqh, *Wql, *Wkh, *Wkl, *Wvh, *Wvl, *Wgh, *Wgl;
    cudaGetSymbolAddress((void**)&xh, g_xh);
    cudaGetSymbolAddress((void**)&xl, g_xl);
    cudaGetSymbolAddress((void**)&Qh, g_Qh);
    cudaGetSymbolAddress((void**)&Ql, g_Ql);
    cudaGetSymbolAddress((void**)&Kh, g_Kh);
    cudaGetSymbolAddress((void**)&Kl, g_Kl);
    cudaGetSymbolAddress((void**)&Vh, g_Vh);
    cudaGetSymbolAddress((void**)&Vl, g_Vl);
    cudaGetSymbolAddress((void**)&Oh, g_Oh);
    cudaGetSymbolAddress((void**)&Ol, g_Ol);
    cudaGetSymbolAddress((void**)&Wqh, g_Wqh);
    cudaGetSymbolAddress((void**)&Wql, g_Wql);
    cudaGetSymbolAddress((void**)&Wkh, g_Wkh);
    cudaGetSymbolAddress((void**)&Wkl, g_Wkl);
    cudaGetSymbolAddress((void**)&Wvh, g_Wvh);
    cudaGetSymbolAddress((void**)&Wvl, g_Wvl);
    cudaGetSymbolAddress((void**)&Wgh, g_Wgh);
    cudaGetSymbolAddress((void**)&Wgl, g_Wgl);

    cudaFuncSetAttribute(attn_bf16_kernel, cudaFuncAttributeMaxDynamicSharedMemorySize,
                         SM_ATTN);
    const int smem_proj = (2 * 64 * WLD + 2 * 2 * 64 * XLD) * 2;
    cudaFuncSetAttribute(proj_mma_kernel, cudaFuncAttributeMaxDynamicSharedMemorySize,
                         smem_proj);

    // 1. split x and weights -> bf16 hi/lo
    const int n4x = NB * CDIM * NN / 4;
    split_kernel<<<(n4x + 255) / 256, 256>>>(
        (const float4*)x, (__nv_bfloat162*)xh, (__nv_bfloat162*)xl, n4x);
    const int n4s = CKD * CDIM / 4, n4b = CDIM * CDIM / 4;
    split_kernel<<<(n4s + 255) / 256, 256>>>(
        (const float4*)wq, (__nv_bfloat162*)Wqh, (__nv_bfloat162*)Wql, n4s);
    split_kernel<<<(n4s + 255) / 256, 256>>>(
        (const float4*)wk, (__nv_bfloat162*)Wkh, (__nv_bfloat162*)Wkl, n4s);
    split_kernel<<<(n4b + 255) / 256, 256>>>(
        (const float4*)wv, (__nv_bfloat162*)Wvh, (__nv_bfloat162*)Wvl, n4b);
    split_kernel<<<(n4b + 255) / 256, 256>>>(
        (const float4*)wg, (__nv_bfloat162*)Wgh, (__nv_bfloat162*)Wgl, n4b);

    // 2. QKV projections on tensor cores (split bf16 out)
    proj_mma_kernel<<<dim3(NN / 128, CKD / 64, NB), 256, smem_proj>>>(
        Wqh, Wql, bq, xh, xl, Qh, Ql, nullptr, CKD);
    proj_mma_kernel<<<dim3(NN / 128, CKD / 64, NB), 256, smem_proj>>>(
        Wkh, Wkl, bk, xh, xl, Kh, Kl, nullptr, CKD);
    proj_mma_kernel<<<dim3(NN / 128, CDIM / 64, NB), 256, smem_proj>>>(
        Wvh, Wvl, bv, xh, xl, Vh, Vl, nullptr, CDIM);

    // 3. Fused attention, 2 CTA/SM (energy never materialized)
    attn_bf16_kernel<<<dim3(NN / 64, NB), 256, SM_ATTN>>>();

    // 4. Final 1x1 conv (wg) -> fp32 output
    proj_mma_kernel<<<dim3(NN / 128, CDIM / 64, NB), 256, smem_proj>>>(
        Wgh, Wgl, bg, Oh, Ol, nullptr, nullptr, out, CDIM);
}

// round 13
// speedup vs baseline: 1.3575x; 1.3575x over previous
#include <cuda_runtime.h>
#include <cuda_bf16.h>
#include <cuda_fp16.h>
#include <math.h>
#include <stdint.h>

#define NB   8
#define CDIM 256
#define CKD  64
#define NN   4096

// ---------------------------------------------------------------------------
// Scratch (allocation-free rule: __device__ globals).
// Projections run in validated 3-term bf16; attention runs in 2-term fp16.
// ---------------------------------------------------------------------------
__device__ __nv_bfloat16 g_xh[NB * CDIM * NN], g_xl[NB * CDIM * NN];
__device__ __half        g_Qh[NB * CKD  * NN], g_Ql[NB * CKD  * NN];
__device__ __half        g_Kh[NB * CKD  * NN];                    // single fp16
__device__ __half        g_Vh[NB * CDIM * NN], g_Vl[NB * CDIM * NN];
__device__ __nv_bfloat16 g_Oh[NB * CDIM * NN], g_Ol[NB * CDIM * NN];
__device__ __nv_bfloat16 g_Wqh[CKD * CDIM],  g_Wql[CKD * CDIM];
__device__ __nv_bfloat16 g_Wkh[CKD * CDIM],  g_Wkl[CKD * CDIM];
__device__ __nv_bfloat16 g_Wvh[CDIM * CDIM], g_Wvl[CDIM * CDIM];
__device__ __nv_bfloat16 g_Wgh[CDIM * CDIM], g_Wgl[CDIM * CDIM];

// ---------------------------------------------------------------------------
// Helpers (fragment maps validated R4-R6)
// ---------------------------------------------------------------------------
__device__ __forceinline__ float elu_scaled(float x) {
    const float invN = 1.0f / 4096.0f;
    return (x > 0.f ? x : (expf(x) - 1.f)) * invN;
}
__device__ __forceinline__ void split2(float x, __nv_bfloat16& h, __nv_bfloat16& l) {
    h = __float2bfloat16(x);
    l = __float2bfloat16(x - __bfloat162float(h));
}
__device__ __forceinline__ void split2h(float x, __half& h, __half& l) {
    h = __float2half(x);
    l = __float2half(x - __half2float(h));
}
__device__ __forceinline__ uint32_t cvta_s(const void* p) {
    return (uint32_t)__cvta_generic_to_shared(p);
}
__device__ __forceinline__ void ldsm_x4(uint32_t* r, uint32_t addr) {
    asm volatile("ldmatrix.sync.aligned.m8n8.x4.shared.b16 {%0,%1,%2,%3},[%4];\n"
                 : "=r"(r[0]), "=r"(r[1]), "=r"(r[2]), "=r"(r[3]) : "r"(addr));
}
__device__ __forceinline__ void ldsm_x4_t(uint32_t* r, uint32_t addr) {
    asm volatile("ldmatrix.sync.aligned.m8n8.x4.trans.shared.b16 {%0,%1,%2,%3},[%4];\n"
                 : "=r"(r[0]), "=r"(r[1]), "=r"(r[2]), "=r"(r[3]) : "r"(addr));
}
__device__ __forceinline__ void mma_bf16(float* c, const uint32_t* a, const uint32_t* b) {
    asm volatile(
        "mma.sync.aligned.m16n8k16.row.col.f32.bf16.bf16.f32 "
        "{%0,%1,%2,%3},{%4,%5,%6,%7},{%8,%9},{%0,%1,%2,%3};\n"
        : "+f"(c[0]), "+f"(c[1]), "+f"(c[2]), "+f"(c[3])
        : "r"(a[0]), "r"(a[1]), "r"(a[2]), "r"(a[3]), "r"(b[0]), "r"(b[1]));
}
__device__ __forceinline__ void mma_fp16(float* c, const uint32_t* a, const uint32_t* b) {
    asm volatile(
        "mma.sync.aligned.m16n8k16.row.col.f32.f16.f16.f32 "
        "{%0,%1,%2,%3},{%4,%5,%6,%7},{%8,%9},{%0,%1,%2,%3};\n"
        : "+f"(c[0]), "+f"(c[1]), "+f"(c[2]), "+f"(c[3])
        : "r"(a[0]), "r"(a[1]), "r"(a[2]), "r"(a[3]), "r"(b[0]), "r"(b[1]));
}
__device__ __forceinline__ void cp16(uint32_t saddr, const void* g) {
    asm volatile("cp.async.cg.shared.global [%0],[%1],16;\n" :: "r"(saddr), "l"(g));
}
__device__ __forceinline__ void cp_commit() {
    asm volatile("cp.async.commit_group;\n" ::: "memory");
}
template <int N> __device__ __forceinline__ void cp_wait() {
    asm volatile("cp.async.wait_group %0;\n" :: "n"(N) : "memory");
}

// ---------------------------------------------------------------------------
// Split fp32 -> bf16 hi/lo (projection inputs/weights).
// ---------------------------------------------------------------------------
__global__ __launch_bounds__(256) void split_kernel(
    const float4* __restrict__ in, __nv_bfloat162* __restrict__ oh,
    __nv_bfloat162* __restrict__ ol, int n4)
{
    int i = blockIdx.x * blockDim.x + threadIdx.x;
    if (i >= n4) return;
    float4 v = in[i];
    __nv_bfloat16 h0, l0, h1, l1, h2, l2, h3, l3;
    split2(v.x, h0, l0); split2(v.y, h1, l1);
    split2(v.z, h2, l2); split2(v.w, h3, l3);
    __nv_bfloat162 a, b;
    a.x = h0; a.y = h1; b.x = h2; b.y = h3;
    oh[i * 2] = a; oh[i * 2 + 1] = b;
    a.x = l0; a.y = l1; b.x = l2; b.y = l3;
    ol[i * 2] = a; ol[i * 2 + 1] = b;
}

// ---------------------------------------------------------------------------
// Tensor-core projection (R6-validated math): Y = W X + bias.
// Output: fp32 (Yf) OR fp16 (Hh, optional Hl split).
// ---------------------------------------------------------------------------
#define WLD 72
#define XLD 136

__global__ __launch_bounds__(256) void proj_mma_kernel(
    const __nv_bfloat16* __restrict__ Wh_g, const __nv_bfloat16* __restrict__ Wl_g,
    const float* __restrict__ bias,
    const __nv_bfloat16* __restrict__ Xh, const __nv_bfloat16* __restrict__ Xl,
    __half* __restrict__ Hh, __half* __restrict__ Hl,
    float* __restrict__ Yf, int R)
{
    extern __shared__ __nv_bfloat16 sp[];
    __nv_bfloat16* Wh   = sp;
    __nv_bfloat16* Wl   = Wh + 64 * WLD;
    __nv_bfloat16* Xbuf = Wl + 64 * WLD;

    const int b  = blockIdx.z;
    const int o0 = blockIdx.y * 64;
    const int n0 = blockIdx.x * 128;
    const int tid  = threadIdx.x;
    const int warp = tid >> 5;
    const int lane = tid & 31;

    const __nv_bfloat16* Xbh = Xh + (size_t)b * CDIM * NN;
    const __nv_bfloat16* Xbl = Xl + (size_t)b * CDIM * NN;

    const uint32_t wh_b = cvta_s(Wh), wl_b = cvta_s(Wl);
    const uint32_t x_b  = cvta_s(Xbuf);
    const uint32_t xstride = 2u * 64 * XLD * 2;

    auto issueX = [&](int kc, int buf) {
#pragma unroll
        for (int r = 0; r < 4; ++r) {
            int idx = tid + r * 256;
            int row = idx >> 4, c4 = idx & 15;
            uint32_t dh = x_b + buf * xstride + (uint32_t)(row * XLD + c4 * 8) * 2;
            cp16(dh, Xbh + (size_t)(kc * 64 + row) * NN + n0 + c4 * 8);
            cp16(dh + 64 * XLD * 2, Xbl + (size_t)(kc * 64 + row) * NN + n0 + c4 * 8);
        }
    };

    const int l7 = lane & 7, rr = lane >> 3;
    const int a_kofs = ((rr & 2) << 2) + l7;
    const int a_mofs = ((rr & 1) << 3);
    const int b_kofs = ((rr & 1) << 3) + l7;
    const int b_nofs = ((rr & 2) << 2);

    const int wo = warp >> 1;
    const int wn = warp & 1;

    float acc[8][4];
#pragma unroll
    for (int t = 0; t < 8; ++t)
#pragma unroll
        for (int e = 0; e < 4; ++e) acc[t][e] = 0.f;

    issueX(0, 0);
    cp_commit();

    for (int kc = 0; kc < 4; ++kc) {
        const int buf = kc & 1;
#pragma unroll
        for (int r = 0; r < 16; ++r) {
            int idx = tid + r * 256;
            int o = idx >> 6, cc = idx & 63;
            Wh[cc * WLD + o] = Wh_g[(size_t)(o0 + o) * CDIM + kc * 64 + cc];
            Wl[cc * WLD + o] = Wl_g[(size_t)(o0 + o) * CDIM + kc * 64 + cc];
        }
        if (kc < 3) { issueX(kc + 1, buf ^ 1); cp_commit(); cp_wait<1>(); }
        else        { cp_wait<0>(); }
        __syncthreads();

        const uint32_t xh_cur = x_b + buf * xstride;
        const uint32_t xl_cur = xh_cur + 64 * XLD * 2;

#pragma unroll
        for (int k0 = 0; k0 < 64; k0 += 16) {
            uint32_t ah[4], al[4];
            uint32_t aoff = (uint32_t)((k0 + a_kofs) * WLD + wo * 16 + a_mofs) * 2;
            ldsm_x4_t(ah, wh_b + aoff);
            ldsm_x4_t(al, wl_b + aoff);
#pragma unroll
            for (int jj = 0; jj < 4; ++jj) {
                uint32_t bh[4], bl[4];
                uint32_t boff =
                    (uint32_t)((k0 + b_kofs) * XLD + wn * 64 + jj * 16 + b_nofs) * 2;
                ldsm_x4_t(bh, xh_cur + boff);
                ldsm_x4_t(bl, xl_cur + boff);
                mma_bf16(acc[jj * 2 + 0], ah, bh + 0);
                mma_bf16(acc[jj * 2 + 0], ah, bl + 0);
                mma_bf16(acc[jj * 2 + 0], al, bh + 0);
                mma_bf16(acc[jj * 2 + 1], ah, bh + 2);
                mma_bf16(acc[jj * 2 + 1], ah, bl + 2);
                mma_bf16(acc[jj * 2 + 1], al, bh + 2);
            }
        }
        __syncthreads();
    }

    const int orow = wo * 16 + (lane >> 2);
    const float b0 = bias[o0 + orow];
    const float b1 = bias[o0 + orow + 8];
#pragma unroll
    for (int t = 0; t < 8; ++t) {
        int col = n0 + wn * 64 + t * 8 + (lane & 3) * 2;
        float v00 = acc[t][0] + b0, v01 = acc[t][1] + b0;
        float v10 = acc[t][2] + b1, v11 = acc[t][3] + b1;
        size_t i0 = ((size_t)b * R + o0 + orow) * NN + col;
        size_t i1 = ((size_t)b * R + o0 + orow + 8) * NN + col;
        if (Yf) {
            *(float2*)&Yf[i0] = make_float2(v00, v01);
            *(float2*)&Yf[i1] = make_float2(v10, v11);
        } else {
            __half h0 = __float2half(v00), h1 = __float2half(v01);
            __half h2 = __float2half(v10), h3 = __float2half(v11);
            *(__half2*)&Hh[i0] = __halves2half2(h0, h1);
            *(__half2*)&Hh[i1] = __halves2half2(h2, h3);
            if (Hl) {
                __half l0 = __float2half(v00 - __half2float(h0));
                __half l1 = __float2half(v01 - __half2float(h1));
                __half l2 = __float2half(v10 - __half2float(h2));
                __half l3 = __float2half(v11 - __half2float(h3));
                *(__half2*)&Hl[i0] = __halves2half2(l0, l1);
                *(__half2*)&Hl[i1] = __halves2half2(l2, l3);
            }
        }
    }
}

// ---------------------------------------------------------------------------
// Fused attention, 2-term fp16. Per CTA: (b, 128 j). i tiled by 64.
//   S = (Qh+Ql)^T Kh        (2 MMAs/tile)
//   P = elu(S)/N -> single fp16 in smem
//   O += (Vh+Vl) P          (2 MMAs/tile)
// R6 pipeline: V(it) overlaps S-phase, Q(it+1) overlaps O-phase.
// smem (halves): Qh 0, Ql 4608, Kh 9216, Ph 17920, Vh 26624, Vl 45056;
// total 63488 halves = 126976 B.
// ---------------------------------------------------------------------------
#define QLDh 72
#define KLDh 136
#define PLDh 136
#define VLDh 72
#define O_QH 0
#define O_QL (64 * QLDh)
#define O_KH (2 * 64 * QLDh)
#define O_PH (O_KH + 64 * KLDh)
#define O_VH (O_PH + 64 * PLDh)
#define O_VL (O_VH + 256 * VLDh)
#define SM_ATTN ((O_VL + 256 * VLDh) * 2)

__global__ __launch_bounds__(512) void attn_fp16_kernel()
{
    extern __shared__ __half smh[];
    const uint32_t sb = cvta_s(smh);

    const int b    = blockIdx.y;
    const int j0g  = blockIdx.x * 128;
    const int tid  = threadIdx.x;
    const int warp = tid >> 5;
    const int lane = tid & 31;

    const __half* Qbh = g_Qh + (size_t)b * CKD * NN;
    const __half* Qbl = g_Ql + (size_t)b * CKD * NN;
    const __half* Kbh = g_Kh + (size_t)b * CKD * NN;
    const __half* Vbh = g_Vh + (size_t)b * CDIM * NN;
    const __half* Vbl = g_Vl + (size_t)b * CDIM * NN;

    const uint32_t qh_b = sb + O_QH * 2;
    const uint32_t ql_b = sb + O_QL * 2;
    const uint32_t kh_b = sb + O_KH * 2;
    const uint32_t ph_b = sb + O_PH * 2;
    const uint32_t vh_b = sb + O_VH * 2;
    const uint32_t vl_b = sb + O_VL * 2;

    // --- cp.async issuers ---
    auto issueQ = [&](int it) {
        int i0 = it * 64;
#pragma unroll
        for (int r = 0; r < 2; ++r) {
            int idx = tid + r * 512;
            int arr = idx >> 9, q = idx & 511;
            int row = q >> 3, c = q & 7;
            uint32_t d = (arr ? ql_b : qh_b) + (uint32_t)(row * QLDh + c * 8) * 2;
            const __half* s = (arr ? Qbl : Qbh) + (size_t)row * NN + i0 + c * 8;
            cp16(d, s);
        }
    };
    auto issueV = [&](int it) {
        int i0 = it * 64;
#pragma unroll
        for (int r = 0; r < 8; ++r) {
            int idx = tid + r * 512;
            int arr = idx >> 11, q = idx & 2047;
            int row = q >> 3, c = q & 7;
            uint32_t d = (arr ? vl_b : vh_b) + (uint32_t)(row * VLDh + c * 8) * 2;
            const __half* s = (arr ? Vbl : Vbh) + (size_t)row * NN + i0 + c * 8;
            cp16(d, s);
        }
    };

    // prologue: Q(0) async + K tile (regular loads, single fp16)
    issueQ(0);
    cp_commit();
#pragma unroll
    for (int r = 0; r < 2; ++r) {
        int idx = tid + r * 512;
        int row = idx >> 4, c16 = idx & 15;
        *(uint4*)&smh[O_KH + row * KLDh + c16 * 8] =
            *(const uint4*)(Kbh + (size_t)row * NN + j0g + c16 * 8);
    }
    cp_wait<0>();
    __syncthreads();

    // ldmatrix lane components (validated R4)
    const int l7 = lane & 7, rr = lane >> 3;
    const int a_dofs = ((rr & 2) << 2) + l7;
    const int a_iofs = ((rr & 1) << 3);
    const int b_kofs = ((rr & 1) << 3) + l7;
    const int b_jofs = ((rr & 2) << 2);
    const int v_row  = (lane & 15);
    const int v_col  = ((lane >> 4) << 3);

    const int s_i0 = (warp >> 2) * 16;            // S: 4 i-blocks of 16
    const int s_jb = (warp & 3) * 32;             // S: 4 j-groups of 32
    const int o_c0 = (warp >> 1) * 32;            // O: 8 c-groups of 32
    const int o_j0 = (warp & 1) * 64;             // O: 2 j-groups of 64

    float oacc[16][4];
#pragma unroll
    for (int t = 0; t < 16; ++t)
#pragma unroll
        for (int e = 0; e < 4; ++e) oacc[t][e] = 0.f;

    for (int it = 0; it < 64; ++it) {
        // V(it) overlaps the S-phase
        issueV(it);
        cp_commit();

        // ---- S = (Qh+Ql)^T Kh (warp: 16i x 32j) ----
        float sacc[4][4];
#pragma unroll
        for (int t = 0; t < 4; ++t)
#pragma unroll
            for (int e = 0; e < 4; ++e) sacc[t][e] = 0.f;

#pragma unroll
        for (int k0 = 0; k0 < 64; k0 += 16) {
            uint32_t ah[4], al[4];
            uint32_t aoff = (uint32_t)((k0 + a_dofs) * QLDh + s_i0 + a_iofs) * 2;
            ldsm_x4_t(ah, qh_b + aoff);
            ldsm_x4_t(al, ql_b + aoff);
#pragma unroll
            for (int jj = 0; jj < 2; ++jj) {
                uint32_t bh[4];
                uint32_t boff =
                    (uint32_t)((k0 + b_kofs) * KLDh + s_jb + jj * 16 + b_jofs) * 2;
                ldsm_x4_t(bh, kh_b + boff);
                mma_fp16(sacc[jj * 2 + 0], ah, bh + 0);
                mma_fp16(sacc[jj * 2 + 1], ah, bh + 2);
                mma_fp16(sacc[jj * 2 + 0], al, bh + 0);
                mma_fp16(sacc[jj * 2 + 1], al, bh + 2);
            }
        }

        // ---- P = elu(S)/N -> single fp16 in smem ----
        {
            int prow = s_i0 + (lane >> 2);
            int pcol = (lane & 3) * 2;
#pragma unroll
            for (int t = 0; t < 4; ++t) {
                int jc = s_jb + t * 8 + pcol;
                __half p0 = __float2half(elu_scaled(sacc[t][0]));
                __half p1 = __float2half(elu_scaled(sacc[t][1]));
                __half p2 = __float2half(elu_scaled(sacc[t][2]));
                __half p3 = __float2half(elu_scaled(sacc[t][3]));
                *(__half2*)&smh[O_PH + prow * PLDh + jc] = __halves2half2(p0, p1);
                *(__half2*)&smh[O_PH + (prow + 8) * PLDh + jc] = __halves2half2(p2, p3);
            }
        }
        cp_wait<0>();        // V(it) arrived
        __syncthreads();     // P visible, Q free

        // Q(it+1) overlaps the O-phase
        if (it < 63) { issueQ(it + 1); cp_commit(); }

        // ---- O += (Vh+Vl) P (warp: 32c x 64j) ----
#pragma unroll
        for (int k0 = 0; k0 < 64; k0 += 16) {
            uint32_t vh0[4], vl0[4], vh1[4], vl1[4];
            {
                uint32_t voff0 = (uint32_t)((o_c0 + v_row) * VLDh + k0 + v_col) * 2;
                uint32_t voff1 = (uint32_t)((o_c0 + 16 + v_row) * VLDh + k0 + v_col) * 2;
                ldsm_x4(vh0, vh_b + voff0);
                ldsm_x4(vl0, vl_b + voff0);
                ldsm_x4(vh1, vh_b + voff1);
                ldsm_x4(vl1, vl_b + voff1);
            }
#pragma unroll
            for (int jj = 0; jj < 4; ++jj) {
                uint32_t ph[4];
                uint32_t poff =
                    (uint32_t)((k0 + b_kofs) * PLDh + o_j0 + jj * 16 + b_jofs) * 2;
                ldsm_x4_t(ph, ph_b + poff);
                mma_fp16(oacc[jj * 2 + 0], vh0, ph + 0);
                mma_fp16(oacc[jj * 2 + 1], vh0, ph + 2);
                mma_fp16(oacc[8 + jj * 2 + 0], vh1, ph + 0);
                mma_fp16(oacc[8 + jj * 2 + 1], vh1, ph + 2);
                mma_fp16(oacc[jj * 2 + 0], vl0, ph + 0);
                mma_fp16(oacc[jj * 2 + 1], vl0, ph + 2);
                mma_fp16(oacc[8 + jj * 2 + 0], vl1, ph + 0);
                mma_fp16(oacc[8 + jj * 2 + 1], vl1, ph + 2);
            }
        }
        cp_wait<0>();        // Q(it+1) arrived
        __syncthreads();     // V/P free
    }

    // ---- store O accumulators, split bf16 (wg-proj input), to scratch ----
#pragma unroll
    for (int cb = 0; cb < 2; ++cb) {
        int orow = o_c0 + cb * 16 + (lane >> 2);
#pragma unroll
        for (int jj = 0; jj < 4; ++jj) {
#pragma unroll
            for (int h = 0; h < 2; ++h) {
                float* a = oacc[cb * 8 + jj * 2 + h];
                int col = j0g + o_j0 + jj * 16 + h * 8 + (lane & 3) * 2;
                size_t i0 = ((size_t)b * CDIM + orow) * NN + col;
                size_t i1 = ((size_t)b * CDIM + orow + 8) * NN + col;
                __nv_bfloat16 h0, l0, h1, l1;
                __nv_bfloat162 th, tl;
                split2(a[0], h0, l0); split2(a[1], h1, l1);
                th.x = h0; th.y = h1; tl.x = l0; tl.y = l1;
                *(__nv_bfloat162*)&g_Oh[i0] = th;
                *(__nv_bfloat162*)&g_Ol[i0] = tl;
                split2(a[2], h0, l0); split2(a[3], h1, l1);
                th.x = h0; th.y = h1; tl.x = l0; tl.y = l1;
                *(__nv_bfloat162*)&g_Oh[i1] = th;
                *(__nv_bfloat162*)&g_Ol[i1] = tl;
            }
        }
    }
}

// ---------------------------------------------------------------------------
extern "C" void kernel_launch(void* const* d_in, const int* in_sizes, int n_in,
                              void* d_out, int out_size)
{
    const float* x  = (const float*)d_in[0];
    const float* wq = (const float*)d_in[1];
    const float* bq = (const float*)d_in[2];
    const float* wk = (const float*)d_in[3];
    const float* bk = (const float*)d_in[4];
    const float* wv = (const float*)d_in[5];
    const float* bv = (const float*)d_in[6];
    const float* wg = (const float*)d_in[7];
    const float* bg = (const float*)d_in[8];
    float* out = (float*)d_out;

    __nv_bfloat16 *xh, *xl, *Oh, *Ol;
    __half *Qh, *Ql, *Kh, *Vh, *Vl;
    __nv_bfloat16 *Wqh, *Wql, *Wkh, *Wkl, *Wvh, *Wvl, *Wgh, *Wgl;
    cudaGetSymbolAddress((void**)&xh, g_xh);
    cudaGetSymbolAddress((void**)&xl, g_xl);
    cudaGetSymbolAddress((void**)&Qh, g_Qh);
    cudaGetSymbolAddress((void**)&Ql, g_Ql);
    cudaGetSymbolAddress((void**)&Kh, g_Kh);
    cudaGetSymbolAddress((void**)&Vh, g_Vh);
    cudaGetSymbolAddress((void**)&Vl, g_Vl);
    cudaGetSymbolAddress((void**)&Oh, g_Oh);
    cudaGetSymbolAddress((void**)&Ol, g_Ol);
    cudaGetSymbolAddress((void**)&Wqh, g_Wqh);
    cudaGetSymbolAddress((void**)&Wql, g_Wql);
    cudaGetSymbolAddress((void**)&Wkh, g_Wkh);
    cudaGetSymbolAddress((void**)&Wkl, g_Wkl);
    cudaGetSymbolAddress((void**)&Wvh, g_Wvh);
    cudaGetSymbolAddress((void**)&Wvl, g_Wvl);
    cudaGetSymbolAddress((void**)&Wgh, g_Wgh);
    cudaGetSymbolAddress((void**)&Wgl, g_Wgl);

    cudaFuncSetAttribute(attn_fp16_kernel, cudaFuncAttributeMaxDynamicSharedMemorySize,
                         SM_ATTN);
    const int smem_proj = (2 * 64 * WLD + 2 * 2 * 64 * XLD) * 2;
    cudaFuncSetAttribute(proj_mma_kernel, cudaFuncAttributeMaxDynamicSharedMemorySize,
                         smem_proj);

    // 1. split x and weights -> bf16 hi/lo (projection operands)
    const int n4x = NB * CDIM * NN / 4;
    split_kernel<<<(n4x + 255) / 256, 256>>>(
        (const float4*)x, (__nv_bfloat162*)xh, (__nv_bfloat162*)xl, n4x);
    const int n4s = CKD * CDIM / 4, n4b = CDIM * CDIM / 4;
    split_kernel<<<(n4s + 255) / 256, 256>>>(
        (const float4*)wq, (__nv_bfloat162*)Wqh, (__nv_bfloat162*)Wql, n4s);
    split_kernel<<<(n4s + 255) / 256, 256>>>(
        (const float4*)wk, (__nv_bfloat162*)Wkh, (__nv_bfloat162*)Wkl, n4s);
    split_kernel<<<(n4b + 255) / 256, 256>>>(
        (const float4*)wv, (__nv_bfloat162*)Wvh, (__nv_bfloat162*)Wvl, n4b);
    split_kernel<<<(n4b + 255) / 256, 256>>>(
        (const float4*)wg, (__nv_bfloat162*)Wgh, (__nv_bfloat162*)Wgl, n4b);

    // 2. QKV projections -> fp16 (Q,V split 2-term; K single)
    proj_mma_kernel<<<dim3(NN / 128, CKD / 64, NB), 256, smem_proj>>>(
        Wqh, Wql, bq, xh, xl, Qh, Ql, nullptr, CKD);
    proj_mma_kernel<<<dim3(NN / 128, CKD / 64, NB), 256, smem_proj>>>(
        Wkh, Wkl, bk, xh, xl, Kh, nullptr, nullptr, CKD);
    proj_mma_kernel<<<dim3(NN / 128, CDIM / 64, NB), 256, smem_proj>>>(
        Wvh, Wvl, bv, xh, xl, Vh, Vl, nullptr, CDIM);

    // 3. Fused attention, 2-term fp16 (energy never materialized)
    attn_fp16_kernel<<<dim3(NN / 128, NB), 512, SM_ATTN>>>();

    // 4. Final 1x1 conv (wg), 3-term bf16 -> fp32 output
    proj_mma_kernel<<<dim3(NN / 128, CDIM / 64, NB), 256, smem_proj>>>(
        Wgh, Wgl, bg, Oh, Ol, nullptr, nullptr, out, CDIM);
}

// round 14
// speedup vs baseline: 2.0619x; 1.5188x over previous
#include <cuda_runtime.h>
#include <cuda_fp16.h>
#include <math.h>
#include <stdint.h>

#define NB   8
#define CDIM 256
#define CKD  64
#define NN   4096

// ---------------------------------------------------------------------------
// Scratch (allocation-free rule: __device__ globals). fp16 pipeline.
// ---------------------------------------------------------------------------
__device__ __half g_xf[NB * CDIM * NN];
__device__ __half g_Qf[NB * CKD  * NN];
__device__ __half g_Kf[NB * CKD  * NN];
__device__ __half g_Vf[NB * CDIM * NN];
__device__ __half g_Of[NB * CDIM * NN];
__device__ __half g_Wqh[CKD * CDIM],  g_Wql[CKD * CDIM];
__device__ __half g_Wkh[CKD * CDIM],  g_Wkl[CKD * CDIM];
__device__ __half g_Wvh[CDIM * CDIM], g_Wvl[CDIM * CDIM];
__device__ __half g_Wgh[CDIM * CDIM], g_Wgl[CDIM * CDIM];

// ---------------------------------------------------------------------------
// Helpers (fragment maps validated R4-R6, fp16 MMA validated R12)
// ---------------------------------------------------------------------------
__device__ __forceinline__ float elu_scaled(float x) {
    const float invN = 1.0f / 4096.0f;
    return (x > 0.f ? x : (expf(x) - 1.f)) * invN;
}
__device__ __forceinline__ void split2h(float x, __half& h, __half& l) {
    h = __float2half(x);
    l = __float2half(x - __half2float(h));
}
__device__ __forceinline__ uint32_t cvta_s(const void* p) {
    return (uint32_t)__cvta_generic_to_shared(p);
}
__device__ __forceinline__ void ldsm_x4(uint32_t* r, uint32_t addr) {
    asm volatile("ldmatrix.sync.aligned.m8n8.x4.shared.b16 {%0,%1,%2,%3},[%4];\n"
                 : "=r"(r[0]), "=r"(r[1]), "=r"(r[2]), "=r"(r[3]) : "r"(addr));
}
__device__ __forceinline__ void ldsm_x4_t(uint32_t* r, uint32_t addr) {
    asm volatile("ldmatrix.sync.aligned.m8n8.x4.trans.shared.b16 {%0,%1,%2,%3},[%4];\n"
                 : "=r"(r[0]), "=r"(r[1]), "=r"(r[2]), "=r"(r[3]) : "r"(addr));
}
__device__ __forceinline__ void mma_fp16(float* c, const uint32_t* a, const uint32_t* b) {
    asm volatile(
        "mma.sync.aligned.m16n8k16.row.col.f32.f16.f16.f32 "
        "{%0,%1,%2,%3},{%4,%5,%6,%7},{%8,%9},{%0,%1,%2,%3};\n"
        : "+f"(c[0]), "+f"(c[1]), "+f"(c[2]), "+f"(c[3])
        : "r"(a[0]), "r"(a[1]), "r"(a[2]), "r"(a[3]), "r"(b[0]), "r"(b[1]));
}
__device__ __forceinline__ void cp16(uint32_t saddr, const void* g) {
    asm volatile("cp.async.cg.shared.global [%0],[%1],16;\n" :: "r"(saddr), "l"(g));
}
__device__ __forceinline__ void cp_commit() {
    asm volatile("cp.async.commit_group;\n" ::: "memory");
}
template <int N> __device__ __forceinline__ void cp_wait() {
    asm volatile("cp.async.wait_group %0;\n" :: "n"(N) : "memory");
}

// ---------------------------------------------------------------------------
// fp32 -> fp16 convert (single) and split (hi/lo).
// ---------------------------------------------------------------------------
__global__ __launch_bounds__(256) void f2h_kernel(
    const float4* __restrict__ in, __half2* __restrict__ o, int n4)
{
    int i = blockIdx.x * blockDim.x + threadIdx.x;
    if (i >= n4) return;
    float4 v = in[i];
    o[i * 2]     = __floats2half2_rn(v.x, v.y);
    o[i * 2 + 1] = __floats2half2_rn(v.z, v.w);
}
__global__ __launch_bounds__(256) void f2h_split_kernel(
    const float4* __restrict__ in, __half2* __restrict__ oh,
    __half2* __restrict__ ol, int n4)
{
    int i = blockIdx.x * blockDim.x + threadIdx.x;
    if (i >= n4) return;
    float4 v = in[i];
    __half h0, l0, h1, l1, h2, l2, h3, l3;
    split2h(v.x, h0, l0); split2h(v.y, h1, l1);
    split2h(v.z, h2, l2); split2h(v.w, h3, l3);
    oh[i * 2]     = __halves2half2(h0, h1);
    oh[i * 2 + 1] = __halves2half2(h2, h3);
    ol[i * 2]     = __halves2half2(l0, l1);
    ol[i * 2 + 1] = __halves2half2(l2, l3);
}

// ---------------------------------------------------------------------------
// fp16 projection: Y[b,o,n] = sum_c W[o,c] X[b,c,n] + bias[o]
// W 2-term fp16 (hi/lo), X single fp16. Output fp16 (Yh) or fp32 (Yf).
// CTA: 64o x 128n, K in 4 chunks of 64, X double-buffered cp.async.
// ---------------------------------------------------------------------------
#define WLD 72
#define XLD 136

__global__ __launch_bounds__(256) void proj_fp16_kernel(
    const __half* __restrict__ Wh_g, const __half* __restrict__ Wl_g,
    const float* __restrict__ bias,
    const __half* __restrict__ Xg,
    __half* __restrict__ Yh, float* __restrict__ Yf, int R)
{
    extern __shared__ __half sp[];
    __half* Wh   = sp;                      // [64][WLD]
    __half* Wl   = Wh + 64 * WLD;
    __half* Xbuf = Wl + 64 * WLD;           // [2][64*XLD]

    const int b  = blockIdx.z;
    const int o0 = blockIdx.y * 64;
    const int n0 = blockIdx.x * 128;
    const int tid  = threadIdx.x;
    const int warp = tid >> 5;
    const int lane = tid & 31;

    const __half* Xb = Xg + (size_t)b * CDIM * NN;

    const uint32_t wh_b = cvta_s(Wh), wl_b = cvta_s(Wl);
    const uint32_t x_b  = cvta_s(Xbuf);
    const uint32_t xstride = 64u * XLD * 2;

    auto issueX = [&](int kc, int buf) {
#pragma unroll
        for (int r = 0; r < 4; ++r) {
            int idx = tid + r * 256;
            int row = idx >> 4, c16 = idx & 15;
            uint32_t d = x_b + buf * xstride + (uint32_t)(row * XLD + c16 * 8) * 2;
            cp16(d, Xb + (size_t)(kc * 64 + row) * NN + n0 + c16 * 8);
        }
    };

    const int l7 = lane & 7, rr = lane >> 3;
    const int a_kofs = ((rr & 2) << 2) + l7;
    const int a_mofs = ((rr & 1) << 3);
    const int b_kofs = ((rr & 1) << 3) + l7;
    const int b_nofs = ((rr & 2) << 2);

    const int wo = warp >> 1;     // 4 o-groups of 16
    const int wn = warp & 1;      // 2 n-groups of 64

    float acc[8][4];
#pragma unroll
    for (int t = 0; t < 8; ++t)
#pragma unroll
        for (int e = 0; e < 4; ++e) acc[t][e] = 0.f;

    issueX(0, 0);
    cp_commit();

    for (int kc = 0; kc < 4; ++kc) {
        const int buf = kc & 1;
#pragma unroll
        for (int r = 0; r < 16; ++r) {
            int idx = tid + r * 256;
            int o = idx >> 6, cc = idx & 63;
            Wh[cc * WLD + o] = Wh_g[(size_t)(o0 + o) * CDIM + kc * 64 + cc];
            Wl[cc * WLD + o] = Wl_g[(size_t)(o0 + o) * CDIM + kc * 64 + cc];
        }
        if (kc < 3) { issueX(kc + 1, buf ^ 1); cp_commit(); cp_wait<1>(); }
        else        { cp_wait<0>(); }
        __syncthreads();

        const uint32_t x_cur = x_b + buf * xstride;

#pragma unroll
        for (int k0 = 0; k0 < 64; k0 += 16) {
            uint32_t ah[4], al[4];
            uint32_t aoff = (uint32_t)((k0 + a_kofs) * WLD + wo * 16 + a_mofs) * 2;
            ldsm_x4_t(ah, wh_b + aoff);
            ldsm_x4_t(al, wl_b + aoff);
#pragma unroll
            for (int jj = 0; jj < 4; ++jj) {
                uint32_t bx[4];
                uint32_t boff =
                    (uint32_t)((k0 + b_kofs) * XLD + wn * 64 + jj * 16 + b_nofs) * 2;
                ldsm_x4_t(bx, x_cur + boff);
                mma_fp16(acc[jj * 2 + 0], ah, bx + 0);
                mma_fp16(acc[jj * 2 + 1], ah, bx + 2);
                mma_fp16(acc[jj * 2 + 0], al, bx + 0);
                mma_fp16(acc[jj * 2 + 1], al, bx + 2);
            }
        }
        __syncthreads();
    }

    const int orow = wo * 16 + (lane >> 2);
    const float b0 = bias[o0 + orow];
    const float b1 = bias[o0 + orow + 8];
#pragma unroll
    for (int t = 0; t < 8; ++t) {
        int col = n0 + wn * 64 + t * 8 + (lane & 3) * 2;
        float v00 = acc[t][0] + b0, v01 = acc[t][1] + b0;
        float v10 = acc[t][2] + b1, v11 = acc[t][3] + b1;
        size_t i0 = ((size_t)b * R + o0 + orow) * NN + col;
        size_t i1 = ((size_t)b * R + o0 + orow + 8) * NN + col;
        if (Yf) {
            *(float2*)&Yf[i0] = make_float2(v00, v01);
            *(float2*)&Yf[i1] = make_float2(v10, v11);
        } else {
            *(__half2*)&Yh[i0] = __floats2half2_rn(v00, v01);
            *(__half2*)&Yh[i1] = __floats2half2_rn(v10, v11);
        }
    }
}

// ---------------------------------------------------------------------------
// Fused attention, single fp16 operands. Per CTA: (b, 128 j). i tiled by 64.
//   S = Q^T K   (1 MMA/tile-term)
//   P = elu(S)/N -> fp16 smem
//   O += V P
// R6 pipeline: V(it) overlaps S-phase, Q(it+1) overlaps O-phase.
// smem (halves): Q 0 (64x72), K 4608 (64x136), P 13312 (64x136),
//                V 22016 (256x72). total 40448 halves = 80896 B.
// ---------------------------------------------------------------------------
#define QLDh 72
#define KLDh 136
#define PLDh 136
#define VLDh 72
#define O_QH 0
#define O_KH (64 * QLDh)
#define O_PH (O_KH + 64 * KLDh)
#define O_VH (O_PH + 64 * PLDh)
#define SM_ATTN ((O_VH + 256 * VLDh) * 2)

__global__ __launch_bounds__(512) void attn_fp16_kernel()
{
    extern __shared__ __half smh[];
    const uint32_t sb = cvta_s(smh);

    const int b    = blockIdx.y;
    const int j0g  = blockIdx.x * 128;
    const int tid  = threadIdx.x;
    const int warp = tid >> 5;
    const int lane = tid & 31;

    const __half* Qb = g_Qf + (size_t)b * CKD * NN;
    const __half* Kb = g_Kf + (size_t)b * CKD * NN;
    const __half* Vb = g_Vf + (size_t)b * CDIM * NN;

    const uint32_t q_b = sb + O_QH * 2;
    const uint32_t k_b = sb + O_KH * 2;
    const uint32_t p_b = sb + O_PH * 2;
    const uint32_t v_b = sb + O_VH * 2;

    // --- cp.async issuers ---
    auto issueQ = [&](int it) {
        int i0 = it * 64;
        int row = tid >> 3, c = tid & 7;
        cp16(q_b + (uint32_t)(row * QLDh + c * 8) * 2,
             Qb + (size_t)row * NN + i0 + c * 8);
    };
    auto issueV = [&](int it) {
        int i0 = it * 64;
#pragma unroll
        for (int r = 0; r < 4; ++r) {
            int idx = tid + r * 512;
            int row = idx >> 3, c = idx & 7;
            cp16(v_b + (uint32_t)(row * VLDh + c * 8) * 2,
                 Vb + (size_t)row * NN + i0 + c * 8);
        }
    };

    // prologue: Q(0) async + K tile (regular loads)
    issueQ(0);
    cp_commit();
#pragma unroll
    for (int r = 0; r < 2; ++r) {
        int idx = tid + r * 512;
        int row = idx >> 4, c16 = idx & 15;
        *(uint4*)&smh[O_KH + row * KLDh + c16 * 8] =
            *(const uint4*)(Kb + (size_t)row * NN + j0g + c16 * 8);
    }
    cp_wait<0>();
    __syncthreads();

    // ldmatrix lane components (validated R4)
    const int l7 = lane & 7, rr = lane >> 3;
    const int a_dofs = ((rr & 2) << 2) + l7;
    const int a_iofs = ((rr & 1) << 3);
    const int b_kofs = ((rr & 1) << 3) + l7;
    const int b_jofs = ((rr & 2) << 2);
    const int v_row  = (lane & 15);
    const int v_col  = ((lane >> 4) << 3);

    const int s_i0 = (warp >> 2) * 16;            // S: 4 i-blocks of 16
    const int s_jb = (warp & 3) * 32;             // S: 4 j-groups of 32
    const int o_c0 = (warp >> 1) * 32;            // O: 8 c-groups of 32
    const int o_j0 = (warp & 1) * 64;             // O: 2 j-groups of 64

    float oacc[16][4];
#pragma unroll
    for (int t = 0; t < 16; ++t)
#pragma unroll
        for (int e = 0; e < 4; ++e) oacc[t][e] = 0.f;

    for (int it = 0; it < 64; ++it) {
        // V(it) overlaps the S-phase
        issueV(it);
        cp_commit();

        // ---- S = Q^T K (warp: 16i x 32j) ----
        float sacc[4][4];
#pragma unroll
        for (int t = 0; t < 4; ++t)
#pragma unroll
            for (int e = 0; e < 4; ++e) sacc[t][e] = 0.f;

#pragma unroll
        for (int k0 = 0; k0 < 64; k0 += 16) {
            uint32_t ah[4];
            uint32_t aoff = (uint32_t)((k0 + a_dofs) * QLDh + s_i0 + a_iofs) * 2;
            ldsm_x4_t(ah, q_b + aoff);
#pragma unroll
            for (int jj = 0; jj < 2; ++jj) {
                uint32_t bh[4];
                uint32_t boff =
                    (uint32_t)((k0 + b_kofs) * KLDh + s_jb + jj * 16 + b_jofs) * 2;
                ldsm_x4_t(bh, k_b + boff);
                mma_fp16(sacc[jj * 2 + 0], ah, bh + 0);
                mma_fp16(sacc[jj * 2 + 1], ah, bh + 2);
            }
        }

        // ---- P = elu(S)/N -> fp16 smem ----
        {
            int prow = s_i0 + (lane >> 2);
            int pcol = (lane & 3) * 2;
#pragma unroll
            for (int t = 0; t < 4; ++t) {
                int jc = s_jb + t * 8 + pcol;
                __half p0 = __float2half(elu_scaled(sacc[t][0]));
                __half p1 = __float2half(elu_scaled(sacc[t][1]));
                __half p2 = __float2half(elu_scaled(sacc[t][2]));
                __half p3 = __float2half(elu_scaled(sacc[t][3]));
                *(__half2*)&smh[O_PH + prow * PLDh + jc] = __halves2half2(p0, p1);
                *(__half2*)&smh[O_PH + (prow + 8) * PLDh + jc] = __halves2half2(p2, p3);
            }
        }
        cp_wait<0>();        // V(it) arrived
        __syncthreads();     // P visible, Q free

        // Q(it+1) overlaps the O-phase
        if (it < 63) { issueQ(it + 1); cp_commit(); }

        // ---- O += V P (warp: 32c x 64j) ----
#pragma unroll
        for (int k0 = 0; k0 < 64; k0 += 16) {
            uint32_t vh0[4], vh1[4];
            {
                uint32_t voff0 = (uint32_t)((o_c0 + v_row) * VLDh + k0 + v_col) * 2;
                uint32_t voff1 = (uint32_t)((o_c0 + 16 + v_row) * VLDh + k0 + v_col) * 2;
                ldsm_x4(vh0, v_b + voff0);
                ldsm_x4(vh1, v_b + voff1);
            }
#pragma unroll
            for (int jj = 0; jj < 4; ++jj) {
                uint32_t ph[4];
                uint32_t poff =
                    (uint32_t)((k0 + b_kofs) * PLDh + o_j0 + jj * 16 + b_jofs) * 2;
                ldsm_x4_t(ph, p_b + poff);
                mma_fp16(oacc[jj * 2 + 0], vh0, ph + 0);
                mma_fp16(oacc[jj * 2 + 1], vh0, ph + 2);
                mma_fp16(oacc[8 + jj * 2 + 0], vh1, ph + 0);
                mma_fp16(oacc[8 + jj * 2 + 1], vh1, ph + 2);
            }
        }
        cp_wait<0>();        // Q(it+1) arrived
        __syncthreads();     // V/P free
    }

    // ---- store O accumulators (single fp16) to scratch ----
#pragma unroll
    for (int cb = 0; cb < 2; ++cb) {
        int orow = o_c0 + cb * 16 + (lane >> 2);
#pragma unroll
        for (int jj = 0; jj < 4; ++jj) {
#pragma unroll
            for (int h = 0; h < 2; ++h) {
                float* a = oacc[cb * 8 + jj * 2 + h];
                int col = j0g + o_j0 + jj * 16 + h * 8 + (lane & 3) * 2;
                size_t i0 = ((size_t)b * CDIM + orow) * NN + col;
                size_t i1 = ((size_t)b * CDIM + orow + 8) * NN + col;
                *(__half2*)&g_Of[i0] = __floats2half2_rn(a[0], a[1]);
                *(__half2*)&g_Of[i1] = __floats2half2_rn(a[2], a[3]);
            }
        }
    }
}

// ---------------------------------------------------------------------------
extern "C" void kernel_launch(void* const* d_in, const int* in_sizes, int n_in,
                              void* d_out, int out_size)
{
    const float* x  = (const float*)d_in[0];
    const float* wq = (const float*)d_in[1];
    const float* bq = (const float*)d_in[2];
    const float* wk = (const float*)d_in[3];
    const float* bk = (const float*)d_in[4];
    const float* wv = (const float*)d_in[5];
    const float* bv = (const float*)d_in[6];
    const float* wg = (const float*)d_in[7];
    const float* bg = (const float*)d_in[8];
    float* out = (float*)d_out;

    __half *xf, *Qf, *Kf, *Vf, *Of;
    __half *Wqh, *Wql, *Wkh, *Wkl, *Wvh, *Wvl, *Wgh, *Wgl;
    cudaGetSymbolAddress((void**)&xf, g_xf);
    cudaGetSymbolAddress((void**)&Qf, g_Qf);
    cudaGetSymbolAddress((void**)&Kf, g_Kf);
    cudaGetSymbolAddress((void**)&Vf, g_Vf);
    cudaGetSymbolAddress((void**)&Of, g_Of);
    cudaGetSymbolAddress((void**)&Wqh, g_Wqh);
    cudaGetSymbolAddress((void**)&Wql, g_Wql);
    cudaGetSymbolAddress((void**)&Wkh, g_Wkh);
    cudaGetSymbolAddress((void**)&Wkl, g_Wkl);
    cudaGetSymbolAddress((void**)&Wvh, g_Wvh);
    cudaGetSymbolAddress((void**)&Wvl, g_Wvl);
    cudaGetSymbolAddress((void**)&Wgh, g_Wgh);
    cudaGetSymbolAddress((void**)&Wgl, g_Wgl);

    cudaFuncSetAttribute(attn_fp16_kernel, cudaFuncAttributeMaxDynamicSharedMemorySize,
                         SM_ATTN);
    const int smem_proj = (2 * 64 * WLD + 2 * 64 * XLD) * 2;
    cudaFuncSetAttribute(proj_fp16_kernel, cudaFuncAttributeMaxDynamicSharedMemorySize,
                         smem_proj);

    // 1. x -> fp16 single; weights -> fp16 hi/lo
    const int n4x = NB * CDIM * NN / 4;
    f2h_kernel<<<(n4x + 255) / 256, 256>>>(
        (const float4*)x, (__half2*)xf, n4x);
    const int n4s = CKD * CDIM / 4, n4b = CDIM * CDIM / 4;
    f2h_split_kernel<<<(n4s + 255) / 256, 256>>>(
        (const float4*)wq, (__half2*)Wqh, (__half2*)Wql, n4s);
    f2h_split_kernel<<<(n4s + 255) / 256, 256>>>(
        (const float4*)wk, (__half2*)Wkh, (__half2*)Wkl, n4s);
    f2h_split_kernel<<<(n4b + 255) / 256, 256>>>(
        (const float4*)wv, (__half2*)Wvh, (__half2*)Wvl, n4b);
    f2h_split_kernel<<<(n4b + 255) / 256, 256>>>(
        (const float4*)wg, (__half2*)Wgh, (__half2*)Wgl, n4b);

    // 2. QKV projections -> single fp16
    proj_fp16_kernel<<<dim3(NN / 128, CKD / 64, NB), 256, smem_proj>>>(
        Wqh, Wql, bq, xf, Qf, nullptr, CKD);
    proj_fp16_kernel<<<dim3(NN / 128, CKD / 64, NB), 256, smem_proj>>>(
        Wkh, Wkl, bk, xf, Kf, nullptr, CKD);
    proj_fp16_kernel<<<dim3(NN / 128, CDIM / 64, NB), 256, smem_proj>>>(
        Wvh, Wvl, bv, xf, Vf, nullptr, CDIM);

    // 3. Fused attention, single fp16 (energy never materialized)
    attn_fp16_kernel<<<dim3(NN / 128, NB), 512, SM_ATTN>>>();

    // 4. Final 1x1 conv (wg) -> fp32 output
    proj_fp16_kernel<<<dim3(NN / 128, CDIM / 64, NB), 256, smem_proj>>>(
        Wgh, Wgl, bg, Of, nullptr, out, CDIM);
}